// round 11
// baseline (speedup 1.0000x reference)
#include <cuda_runtime.h>
#include <cuda_bf16.h>
#include <cuda_fp16.h>
#include <cstdint>

#define F      128
#define H      128
#define DEG    16
#define KDIM   256
#define NMAX   131072
#define BMAX   16384
#define PITCH  136            // fp16/row gemm1 (K=128); 272 B ≡ 4 words (mod 32) -> conflict-free
#define ROWB   272
#define HSLAB  (64 * ROWB)    // 17408 B  (64-row A half-slab)
#define SLAB   (128 * ROWB)   // 34816 B  (128-n B slab)
#define ABUF_T (2 * HSLAB)    // 34816 B  (A: 2 buffers)
#define SMEM_G1 (ABUF_T + 2 * SLAB)   // 104448 B -> 2 CTAs/SM

#define PITCH2 264            // fp16/row gemm2 (K=256); 528 B ≡ 4 words (mod 32)
#define ROWB2  528
#define A2SLAB (64 * ROWB2)   // 33792 B
#define B2SLAB (128 * ROWB2)  // 67584 B per lvl
#define SMEM_G2 (A2SLAB + 2 * B2SLAB)  // 168960 B

// ---------------- scratch (all intermediates fp16; Yt/Yb/h1/x2 in PERMUTED col layout) ----
__device__ __half g_Yt[(size_t)NMAX * 128];     // f @ w1_top
__device__ __half g_Yb[(size_t)NMAX * 128];     // f @ w1_bot (gathered)
__device__ __half g_h1[(size_t)NMAX * 128];     // layer-1 embeddings (flagged rows only)
__device__ __half g_B1img[2][128 * PITCH];      // [ch][n][k]   (w1 fp16)
__device__ __half g_B2img[2][128 * PITCH2];     // [lvl][n][p]  (w2 hi/lo fp16, k-rows permuted)
__device__ __half g_x2[(size_t)BMAX * 256];     // layer2 input (fp16)
__device__ unsigned char g_flag[NMAX];          // 1 if h1 row is referenced by layer-2

// ---------------- PTX helpers ----------------
__device__ __forceinline__ void mma16816h(float* c, const uint32_t* a, const uint32_t* b) {
    asm volatile(
        "mma.sync.aligned.m16n8k16.row.col.f32.f16.f16.f32 "
        "{%0,%1,%2,%3}, {%4,%5,%6,%7}, {%8,%9}, {%0,%1,%2,%3};"
        : "+f"(c[0]), "+f"(c[1]), "+f"(c[2]), "+f"(c[3])
        : "r"(a[0]), "r"(a[1]), "r"(a[2]), "r"(a[3]), "r"(b[0]), "r"(b[1]));
}
__device__ __forceinline__ void ldsm4(uint32_t* r, uint32_t addr) {
    asm volatile("ldmatrix.sync.aligned.m8n8.x4.shared.b16 {%0,%1,%2,%3}, [%4];"
        : "=r"(r[0]), "=r"(r[1]), "=r"(r[2]), "=r"(r[3]) : "r"(addr));
}
__device__ __forceinline__ uint32_t smem_u32(const void* p) {
    return (uint32_t)__cvta_generic_to_shared(p);
}
__device__ __forceinline__ void split_fp16(float v, __half& hi, __half& lo) {
    hi = __float2half_rn(v);
    lo = __float2half_rn(v - __half2float(hi));
}
__device__ __forceinline__ uint32_t h2bits(__half2 h) {
    return *reinterpret_cast<uint32_t*>(&h);
}

// ---------------- kernel 1: build fp16 weight images + scatter h1-needed flags ----------------
// w1: B1img[ch][n][k] = f16(w1[ch*128+k][n])
// w2: B2img[lvl][n][p] = split(w2[sigma2(p)][n]) with
//     sigma(p127) = (p127&64) + ((p127>>1)&7)*8 + ((p127>>4)&3)*2 + (p127&1)
// flags: for each batch node, mark self + its DEG neighbors
__global__ void prep_kernel(const float* __restrict__ w1, const float* __restrict__ w2,
                            const int* __restrict__ nodes, const int* __restrict__ nbr,
                            unsigned char* __restrict__ flag, int B)
{
    int i = blockIdx.x * 256 + threadIdx.x;
    if (i < 32768) {
        int ch = i >> 14, n = (i >> 7) & 127, k = i & 127;
        float v = w1[(size_t)(ch * 128 + k) * 128 + n];
        g_B1img[ch][n * PITCH + k] = __float2half_rn(v);
    } else if (i < 65536) {
        int j = i - 32768;
        int n = j & 127, p = j >> 7;                 // p = storage k-index 0..255
        int p1  = p & 127;
        int sig = (p1 & 64) + ((p1 >> 1) & 7) * 8 + ((p1 >> 4) & 3) * 2 + (p1 & 1);
        int k   = (p & 128) + sig;
        float v = w2[(size_t)k * 128 + n];
        __half hb, lb;
        split_fp16(v, hb, lb);
        g_B2img[0][n * PITCH2 + p] = hb;
        g_B2img[1][n * PITCH2 + p] = lb;
    } else {
        int b = i - 65536;
        if (b < B) {
            int s = __ldg(nodes + b);
            flag[s] = 1;
            const int* nb = nbr + (size_t)s * DEG;
            #pragma unroll
            for (int d = 0; d < DEG; d++) flag[__ldg(nb + d)] = 1;
        }
    }
}

// ---------------- kernel 2: gemm1  Y[N,256] = f16(f)[N,128] @ f16(w1) ----------------
// Outputs stored fp16 in permuted col layout: storage col = (chunk64) + tig*16 + nb*2 + e.
// smem: A[buf2] @ buf*HSLAB ; B[ch2] @ ABUF_T + ch*SLAB
__global__ void __launch_bounds__(256, 2) gemm1_kernel(
    const float* __restrict__ f, __half* __restrict__ Yt, __half* __restrict__ Yb,
    int nRows, int nHT)
{
    extern __shared__ unsigned char smem[];
    const int tid = threadIdx.x, wid = tid >> 5, lid = tid & 31;
    const int g   = lid >> 2, tig = lid & 3;
    const int warp_m = wid & 1, warp_n = wid >> 1;       // 2 x 32 rows, 4 x 64 cols
    const int chn = warp_n >> 1, ncl = (warp_n & 1) * 64;
    const uint32_t smem_base = smem_u32(smem);

    const int offA = ((lid & 7) + ((lid >> 3) & 1) * 8) * ROWB + (lid >> 4) * 16;
    const int offB = ((lid & 7) + (lid >> 4) * 8) * ROWB + ((lid >> 3) & 1) * 16;

    // stage both B slabs (g_B1img contiguous [ch])
    {
        const uint4* src = (const uint4*)&g_B1img[0][0];
        uint4* dst = (uint4*)(smem + ABUF_T);
        #pragma unroll 4
        for (int i = tid; i < 2 * SLAB / 16; i += 256) dst[i] = src[i];
    }

    const int r_st = tid >> 5;          // row in 8-row group
    const int k_st = (tid & 31) * 4;    // k0 elements

    float4 Rst[8];
    auto LOADHT = [&](int ht) {
        const int base = ht * 64;
        #pragma unroll
        for (int j = 0; j < 8; j++) {
            int grow = base + j * 8 + r_st;
            Rst[j] = (grow < nRows) ? *(const float4*)(f + (size_t)grow * 128 + k_st)
                                    : make_float4(0.f, 0.f, 0.f, 0.f);
        }
    };
    auto STOREHT = [&](int buf) {
        unsigned char* Ah = smem + buf * HSLAB;
        #pragma unroll
        for (int j = 0; j < 8; j++) {
            uint2 u;
            u.x = h2bits(__floats2half2_rn(Rst[j].x, Rst[j].y));
            u.y = h2bits(__floats2half2_rn(Rst[j].z, Rst[j].w));
            int r = j * 8 + r_st;
            *(uint2*)(Ah + r * ROWB + k_st * 2) = u;
        }
    };

    int cur = 0;
    int ht = blockIdx.x;
    if (ht < nHT) { LOADHT(ht); STOREHT(0); }
    __syncthreads();

    while (ht < nHT) {
        const int htn  = ht + gridDim.x;
        const int base = ht * 64;

        if (htn < nHT) LOADHT(htn);

        float acc[2][8][4];
        #pragma unroll
        for (int mb = 0; mb < 2; mb++)
            #pragma unroll
            for (int nb = 0; nb < 8; nb++)
                #pragma unroll
                for (int q = 0; q < 4; q++) acc[mb][nb][q] = 0.f;

        const uint32_t Abase = smem_base + cur * HSLAB + warp_m * 32 * ROWB + offA;
        const uint32_t Bbase = smem_base + ABUF_T + chn * SLAB + ncl * ROWB + offB;
        #pragma unroll
        for (int ks = 0; ks < 8; ks++) {
            const int kB = ks * 32;
            uint32_t a[2][4];
            ldsm4(a[0], Abase + kB);
            ldsm4(a[1], Abase + 16 * ROWB + kB);
            uint32_t b[4][4];
            #pragma unroll
            for (int pr = 0; pr < 4; pr++)
                ldsm4(b[pr], Bbase + pr * 16 * ROWB + kB);
            #pragma unroll
            for (int mb = 0; mb < 2; mb++)
                #pragma unroll
                for (int pr = 0; pr < 4; pr++) {
                    mma16816h(acc[mb][pr * 2],     a[mb], &b[pr][0]);
                    mma16816h(acc[mb][pr * 2 + 1], a[mb], &b[pr][2]);
                }
        }

        // permuted epilogue: 16 contiguous halfs per (thread, row) -> 2x STG.128
        __half* dst = (chn == 0) ? Yt : Yb;
        const int colp = (warp_n & 1) * 64 + tig * 16;
        #pragma unroll
        for (int mb = 0; mb < 2; mb++) {
            int row0 = base + warp_m * 32 + mb * 16 + g;
            if (row0 < nRows) {
                uint4 v0 = make_uint4(
                    h2bits(__floats2half2_rn(acc[mb][0][0], acc[mb][0][1])),
                    h2bits(__floats2half2_rn(acc[mb][1][0], acc[mb][1][1])),
                    h2bits(__floats2half2_rn(acc[mb][2][0], acc[mb][2][1])),
                    h2bits(__floats2half2_rn(acc[mb][3][0], acc[mb][3][1])));
                uint4 v1 = make_uint4(
                    h2bits(__floats2half2_rn(acc[mb][4][0], acc[mb][4][1])),
                    h2bits(__floats2half2_rn(acc[mb][5][0], acc[mb][5][1])),
                    h2bits(__floats2half2_rn(acc[mb][6][0], acc[mb][6][1])),
                    h2bits(__floats2half2_rn(acc[mb][7][0], acc[mb][7][1])));
                *(uint4*)(dst + (size_t)row0 * 128 + colp)     = v0;
                *(uint4*)(dst + (size_t)row0 * 128 + colp + 8) = v1;
            }
            if (row0 + 8 < nRows) {
                uint4 v0 = make_uint4(
                    h2bits(__floats2half2_rn(acc[mb][0][2], acc[mb][0][3])),
                    h2bits(__floats2half2_rn(acc[mb][1][2], acc[mb][1][3])),
                    h2bits(__floats2half2_rn(acc[mb][2][2], acc[mb][2][3])),
                    h2bits(__floats2half2_rn(acc[mb][3][2], acc[mb][3][3])));
                uint4 v1 = make_uint4(
                    h2bits(__floats2half2_rn(acc[mb][4][2], acc[mb][4][3])),
                    h2bits(__floats2half2_rn(acc[mb][5][2], acc[mb][5][3])),
                    h2bits(__floats2half2_rn(acc[mb][6][2], acc[mb][6][3])),
                    h2bits(__floats2half2_rn(acc[mb][7][2], acc[mb][7][3])));
                *(uint4*)(dst + (size_t)(row0 + 8) * 128 + colp)     = v0;
                *(uint4*)(dst + (size_t)(row0 + 8) * 128 + colp + 8) = v1;
            }
        }

        if (htn < nHT) STOREHT(cur ^ 1);
        __syncthreads();
        cur ^= 1;
        ht = htn;
    }
}

// ---------------- kernel 3: agg1  h1[i] = f16(Yt[i] + mean_d Yb[nbr[i][d]]) — flagged rows only ----
__global__ void __launch_bounds__(256) agg1_kernel(
    const __half* __restrict__ Yt, const __half* __restrict__ Yb,
    const int* __restrict__ nbr, const unsigned char* __restrict__ flag,
    __half* __restrict__ h1, int N)
{
    int wid = threadIdx.x >> 5, lid = threadIdx.x & 31;
    int node = blockIdx.x * 8 + wid;
    if (node >= N || !flag[node]) return;
    const int* nb = nbr + (size_t)node * DEG;
    float a0 = 0.f, a1 = 0.f, a2 = 0.f, a3 = 0.f;
    #pragma unroll
    for (int d = 0; d < DEG; d++) {
        int j = __ldg(nb + d);
        uint2 u = *(const uint2*)(Yb + (size_t)j * 128 + lid * 4);
        float2 f0 = __half22float2(*reinterpret_cast<__half2*>(&u.x));
        float2 f1 = __half22float2(*reinterpret_cast<__half2*>(&u.y));
        a0 += f0.x; a1 += f0.y; a2 += f1.x; a3 += f1.y;
    }
    uint2 t = *(const uint2*)(Yt + (size_t)node * 128 + lid * 4);
    float2 t0 = __half22float2(*reinterpret_cast<__half2*>(&t.x));
    float2 t1 = __half22float2(*reinterpret_cast<__half2*>(&t.y));
    uint2 o;
    o.x = h2bits(__floats2half2_rn(t0.x + a0 * 0.0625f, t0.y + a1 * 0.0625f));
    o.y = h2bits(__floats2half2_rn(t1.x + a2 * 0.0625f, t1.y + a3 * 0.0625f));
    *(uint2*)(h1 + (size_t)node * 128 + lid * 4) = o;
}

// ---------------- kernel 4: agg2  x2[b] = [h1[nodes[b]], f16(mean(h1[nbr]))] ----------------
__global__ void __launch_bounds__(256) agg2_kernel(
    const __half* __restrict__ h1, const int* __restrict__ nbr,
    const int* __restrict__ nodes, __half* __restrict__ x2, int B)
{
    int wid = threadIdx.x >> 5, lid = threadIdx.x & 31;
    int b = blockIdx.x * 8 + wid;
    if (b >= B) return;
    int self = __ldg(nodes + b);

    uint2 sv = *(const uint2*)(h1 + (size_t)self * 128 + lid * 4);   // bit-copy self half

    const int* nb = nbr + (size_t)self * DEG;
    float a0 = 0.f, a1 = 0.f, a2 = 0.f, a3 = 0.f;
    #pragma unroll
    for (int d = 0; d < DEG; d++) {
        int j = __ldg(nb + d);
        uint2 u = *(const uint2*)(h1 + (size_t)j * 128 + lid * 4);
        float2 f0 = __half22float2(*reinterpret_cast<__half2*>(&u.x));
        float2 f1 = __half22float2(*reinterpret_cast<__half2*>(&u.y));
        a0 += f0.x; a1 += f0.y; a2 += f1.x; a3 += f1.y;
    }
    a0 *= 0.0625f; a1 *= 0.0625f; a2 *= 0.0625f; a3 *= 0.0625f;

    size_t base = (size_t)b * 256;
    *(uint2*)(x2 + base + lid * 4) = sv;
    *(uint2*)(x2 + base + 128 + lid * 4) =
        make_uint2(h2bits(__floats2half2_rn(a0, a1)),
                   h2bits(__floats2half2_rn(a2, a3)));
}

// ---------------- kernel 5: gemm2  out[B,128] = x2[B,256] @ (w2h + w2l) ----------------
// smem: A @ 0 ; B[lvl2] @ A2SLAB + lvl*B2SLAB
__global__ void __launch_bounds__(256, 1) gemm2_kernel(
    const __half* __restrict__ x2, float* __restrict__ out, int B)
{
    extern __shared__ unsigned char smem[];
    const int tid = threadIdx.x, wid = tid >> 5, lid = tid & 31;
    const int g   = lid >> 2, tig = lid & 3;
    const int warp_m = wid & 1, warp_n = wid >> 1;   // 2 x 32 rows, 4 x 32 cols
    const uint32_t smem_base = smem_u32(smem);
    const int base = blockIdx.x * 64;

    const int offA = ((lid & 7) + ((lid >> 3) & 1) * 8) * ROWB2 + (lid >> 4) * 16;
    const int offB = ((lid & 7) + (lid >> 4) * 8) * ROWB2 + ((lid >> 3) & 1) * 16;

    // stage B (both levels, contiguous image)
    {
        const uint4* src = (const uint4*)&g_B2img[0][0];
        uint4* dst = (uint4*)(smem + A2SLAB);
        #pragma unroll 4
        for (int i = tid; i < 2 * B2SLAB / 16; i += 256) dst[i] = src[i];
    }
    // stage A: 64 rows x 512B, pitched to 528
    {
        int r = tid >> 2, q = tid & 3;               // r 0..63, 128B quarter
        int grow = base + r;
        const uint4* sh = (const uint4*)(x2 + (size_t)grow * 256) + q * 8;
        uint4* dh = (uint4*)(smem + r * ROWB2 + q * 128);
        if (grow < B) {
            #pragma unroll
            for (int j = 0; j < 8; j++) dh[j] = sh[j];
        } else {
            uint4 z = make_uint4(0, 0, 0, 0);
            #pragma unroll
            for (int j = 0; j < 8; j++) dh[j] = z;
        }
    }
    __syncthreads();

    float acc[2][4][4];
    #pragma unroll
    for (int mb = 0; mb < 2; mb++)
        #pragma unroll
        for (int nb = 0; nb < 4; nb++)
            #pragma unroll
            for (int q = 0; q < 4; q++) acc[mb][nb][q] = 0.f;

    #pragma unroll
    for (int p = 0; p < 2; p++) {
        const uint32_t Abase = smem_base + warp_m * 32 * ROWB2 + offA;
        const uint32_t Bbase = smem_base + A2SLAB + p * B2SLAB
                             + warp_n * 32 * ROWB2 + offB;
        #pragma unroll
        for (int ks = 0; ks < 16; ks++) {
            const int kB = ks * 32;
            uint32_t a[2][4];
            ldsm4(a[0], Abase + kB);
            ldsm4(a[1], Abase + 16 * ROWB2 + kB);
            uint32_t b[2][4];
            ldsm4(b[0], Bbase + kB);
            ldsm4(b[1], Bbase + 16 * ROWB2 + kB);
            #pragma unroll
            for (int mb = 0; mb < 2; mb++)
                #pragma unroll
                for (int pr = 0; pr < 2; pr++) {
                    mma16816h(acc[mb][pr * 2],     a[mb], &b[pr][0]);
                    mma16816h(acc[mb][pr * 2 + 1], a[mb], &b[pr][2]);
                }
        }
    }

    #pragma unroll
    for (int mb = 0; mb < 2; mb++) {
        int row0 = base + warp_m * 32 + mb * 16 + g;
        #pragma unroll
        for (int nb = 0; nb < 4; nb++) {
            int col = warp_n * 32 + nb * 8 + tig * 2;
            if (row0 < B)
                *(float2*)(out + (size_t)row0 * 128 + col) =
                    make_float2(acc[mb][nb][0], acc[mb][nb][1]);
            if (row0 + 8 < B)
                *(float2*)(out + (size_t)(row0 + 8) * 128 + col) =
                    make_float2(acc[mb][nb][2], acc[mb][nb][3]);
        }
    }
}

// ---------------- host ----------------
extern "C" void kernel_launch(void* const* d_in, const int* in_sizes, int n_in,
                              void* d_out, int out_size)
{
    const float* features     = (const float*)d_in[0];
    const float* w1           = (const float*)d_in[1];
    const float* w2           = (const float*)d_in[2];
    const int*   neighbor_idx = (const int*)d_in[3];
    const int*   nodes        = (const int*)d_in[4];
    float*       out          = (float*)d_out;

    const int N = in_sizes[0] / F;
    const int B = in_sizes[4];

    __half *Yt, *Yb, *h1p, *x2;
    unsigned char* flag;
    cudaGetSymbolAddress((void**)&Yt,   g_Yt);
    cudaGetSymbolAddress((void**)&Yb,   g_Yb);
    cudaGetSymbolAddress((void**)&h1p,  g_h1);
    cudaGetSymbolAddress((void**)&x2,   g_x2);
    cudaGetSymbolAddress((void**)&flag, g_flag);

    // 0) clear flags (graph-capturable async memset, no allocation)
    cudaMemsetAsync(flag, 0, NMAX);

    // 1) weight images + flag scatter
    prep_kernel<<<(65536 + BMAX + 255) / 256, 256>>>(w1, w2, nodes, neighbor_idx, flag, B);

    // 2) gemm1: Yt / Yb for all N  (2 CTAs/SM)
    const int nHT = (N + 63) / 64;
    cudaFuncSetAttribute(gemm1_kernel, cudaFuncAttributeMaxDynamicSharedMemorySize, SMEM_G1);
    gemm1_kernel<<<296, 256, SMEM_G1>>>(features, Yt, Yb, N, nHT);

    // 3) agg1 -> h1 (fp16), flagged rows only
    agg1_kernel<<<(N + 7) / 8, 256>>>(Yt, Yb, neighbor_idx, flag, h1p, N);

    // 4) agg2 -> x2 (fp16)
    agg2_kernel<<<(B + 7) / 8, 256>>>(h1p, neighbor_idx, nodes, x2, B);

    // 5) gemm2 -> out
    cudaFuncSetAttribute(gemm2_kernel, cudaFuncAttributeMaxDynamicSharedMemorySize, SMEM_G2);
    gemm2_kernel<<<(B + 63) / 64, 256, SMEM_G2>>>(x2, out, B);
}

// round 12
// speedup vs baseline: 1.0444x; 1.0444x over previous
#include <cuda_runtime.h>
#include <cuda_bf16.h>
#include <cuda_fp16.h>
#include <cstdint>

#define F      128
#define H      128
#define DEG    16
#define KDIM   256
#define NMAX   131072
#define BMAX   16384
#define PITCH  136            // fp16/row gemm1 (K=128); 272 B ≡ 4 words (mod 32) -> conflict-free
#define ROWB   272
#define HSLAB  (64 * ROWB)    // 17408 B  (64-row A half-slab)
#define SLAB   (128 * ROWB)   // 34816 B  (128-n B slab)
#define ABUF_T (2 * HSLAB)    // 34816 B  (A: 2 buffers)
#define SMEM_G1 (ABUF_T + 2 * SLAB)   // 104448 B -> 2 CTAs/SM

#define PITCH2 264            // fp16/row gemm2 (K=256); 528 B ≡ 4 words (mod 32)
#define ROWB2  528
#define A2SLAB (64 * ROWB2)   // 33792 B
#define B2SLAB (128 * ROWB2)  // 67584 B per lvl
#define SMEM_G2 (A2SLAB + 2 * B2SLAB)  // 168960 B

// ---------------- scratch (all intermediates fp16; Yt/Yb/h1/x2 in PERMUTED col layout) ----
__device__ __half g_Yt[(size_t)NMAX * 128];     // f @ w1_top  (streamed, evict-first)
__device__ __half g_Yb[(size_t)NMAX * 128];     // f @ w1_bot  (gathered, keep L2-resident)
__device__ __half g_h1[(size_t)NMAX * 128];     // layer-1 embeddings
__device__ __half g_B1img[2][128 * PITCH];      // [ch][n][k]   (w1 fp16)
__device__ __half g_B2img[2][128 * PITCH2];     // [lvl][n][p]  (w2 hi/lo fp16, k-rows permuted)
__device__ __half g_x2[(size_t)BMAX * 256];     // layer2 input (fp16)

// ---------------- PTX helpers ----------------
__device__ __forceinline__ void mma16816h(float* c, const uint32_t* a, const uint32_t* b) {
    asm volatile(
        "mma.sync.aligned.m16n8k16.row.col.f32.f16.f16.f32 "
        "{%0,%1,%2,%3}, {%4,%5,%6,%7}, {%8,%9}, {%0,%1,%2,%3};"
        : "+f"(c[0]), "+f"(c[1]), "+f"(c[2]), "+f"(c[3])
        : "r"(a[0]), "r"(a[1]), "r"(a[2]), "r"(a[3]), "r"(b[0]), "r"(b[1]));
}
__device__ __forceinline__ void ldsm4(uint32_t* r, uint32_t addr) {
    asm volatile("ldmatrix.sync.aligned.m8n8.x4.shared.b16 {%0,%1,%2,%3}, [%4];"
        : "=r"(r[0]), "=r"(r[1]), "=r"(r[2]), "=r"(r[3]) : "r"(addr));
}
__device__ __forceinline__ uint32_t smem_u32(const void* p) {
    return (uint32_t)__cvta_generic_to_shared(p);
}
__device__ __forceinline__ void split_fp16(float v, __half& hi, __half& lo) {
    hi = __float2half_rn(v);
    lo = __float2half_rn(v - __half2float(hi));
}
__device__ __forceinline__ uint32_t h2bits(__half2 h) {
    return *reinterpret_cast<uint32_t*>(&h);
}

// ---------------- kernel 1: build fp16 weight images ----------------
// w1: B1img[ch][n][k] = f16(w1[ch*128+k][n])
// w2: B2img[lvl][n][p] = split(w2[sigma2(p)][n]) with
//     sigma(p127) = (p127&64) + ((p127>>1)&7)*8 + ((p127>>4)&3)*2 + (p127&1)
__global__ void prep_kernel(const float* __restrict__ w1, const float* __restrict__ w2) {
    int i = blockIdx.x * 256 + threadIdx.x;          // 65536 total
    if (i < 32768) {
        int ch = i >> 14, n = (i >> 7) & 127, k = i & 127;
        float v = w1[(size_t)(ch * 128 + k) * 128 + n];
        g_B1img[ch][n * PITCH + k] = __float2half_rn(v);
    } else if (i < 65536) {
        int j = i - 32768;
        int n = j & 127, p = j >> 7;                 // p = storage k-index 0..255
        int p1  = p & 127;
        int sig = (p1 & 64) + ((p1 >> 1) & 7) * 8 + ((p1 >> 4) & 3) * 2 + (p1 & 1);
        int k   = (p & 128) + sig;
        float v = w2[(size_t)k * 128 + n];
        __half hb, lb;
        split_fp16(v, hb, lb);
        g_B2img[0][n * PITCH2 + p] = hb;
        g_B2img[1][n * PITCH2 + p] = lb;
    }
}

// ---------------- kernel 2: gemm1  Y[N,256] = f16(f)[N,128] @ f16(w1) ----------------
// Outputs stored fp16 in permuted col layout: storage col = (chunk64) + tig*16 + nb*2 + e.
// Yt stored evict-first (only streamed once by agg1); Yb default (gathered 16x).
// smem: A[buf2] @ buf*HSLAB ; B[ch2] @ ABUF_T + ch*SLAB
__global__ void __launch_bounds__(256, 2) gemm1_kernel(
    const float* __restrict__ f, __half* __restrict__ Yt, __half* __restrict__ Yb,
    int nRows, int nHT)
{
    extern __shared__ unsigned char smem[];
    const int tid = threadIdx.x, wid = tid >> 5, lid = tid & 31;
    const int g   = lid >> 2, tig = lid & 3;
    const int warp_m = wid & 1, warp_n = wid >> 1;       // 2 x 32 rows, 4 x 64 cols
    const int chn = warp_n >> 1, ncl = (warp_n & 1) * 64;
    const uint32_t smem_base = smem_u32(smem);

    const int offA = ((lid & 7) + ((lid >> 3) & 1) * 8) * ROWB + (lid >> 4) * 16;
    const int offB = ((lid & 7) + (lid >> 4) * 8) * ROWB + ((lid >> 3) & 1) * 16;

    // stage both B slabs (g_B1img contiguous [ch])
    {
        const uint4* src = (const uint4*)&g_B1img[0][0];
        uint4* dst = (uint4*)(smem + ABUF_T);
        #pragma unroll 4
        for (int i = tid; i < 2 * SLAB / 16; i += 256) dst[i] = src[i];
    }

    const int r_st = tid >> 5;          // row in 8-row group
    const int k_st = (tid & 31) * 4;    // k0 elements

    float4 Rst[8];
    auto LOADHT = [&](int ht) {
        const int base = ht * 64;
        #pragma unroll
        for (int j = 0; j < 8; j++) {
            int grow = base + j * 8 + r_st;
            Rst[j] = (grow < nRows) ? *(const float4*)(f + (size_t)grow * 128 + k_st)
                                    : make_float4(0.f, 0.f, 0.f, 0.f);
        }
    };
    auto STOREHT = [&](int buf) {
        unsigned char* Ah = smem + buf * HSLAB;
        #pragma unroll
        for (int j = 0; j < 8; j++) {
            uint2 u;
            u.x = h2bits(__floats2half2_rn(Rst[j].x, Rst[j].y));
            u.y = h2bits(__floats2half2_rn(Rst[j].z, Rst[j].w));
            int r = j * 8 + r_st;
            *(uint2*)(Ah + r * ROWB + k_st * 2) = u;
        }
    };

    int cur = 0;
    int ht = blockIdx.x;
    if (ht < nHT) { LOADHT(ht); STOREHT(0); }
    __syncthreads();

    while (ht < nHT) {
        const int htn  = ht + gridDim.x;
        const int base = ht * 64;

        if (htn < nHT) LOADHT(htn);

        float acc[2][8][4];
        #pragma unroll
        for (int mb = 0; mb < 2; mb++)
            #pragma unroll
            for (int nb = 0; nb < 8; nb++)
                #pragma unroll
                for (int q = 0; q < 4; q++) acc[mb][nb][q] = 0.f;

        const uint32_t Abase = smem_base + cur * HSLAB + warp_m * 32 * ROWB + offA;
        const uint32_t Bbase = smem_base + ABUF_T + chn * SLAB + ncl * ROWB + offB;
        #pragma unroll
        for (int ks = 0; ks < 8; ks++) {
            const int kB = ks * 32;
            uint32_t a[2][4];
            ldsm4(a[0], Abase + kB);
            ldsm4(a[1], Abase + 16 * ROWB + kB);
            uint32_t b[4][4];
            #pragma unroll
            for (int pr = 0; pr < 4; pr++)
                ldsm4(b[pr], Bbase + pr * 16 * ROWB + kB);
            #pragma unroll
            for (int mb = 0; mb < 2; mb++)
                #pragma unroll
                for (int pr = 0; pr < 4; pr++) {
                    mma16816h(acc[mb][pr * 2],     a[mb], &b[pr][0]);
                    mma16816h(acc[mb][pr * 2 + 1], a[mb], &b[pr][2]);
                }
        }

        // permuted epilogue: 16 contiguous halfs per (thread, row) -> 2x STG.128
        __half* dst = (chn == 0) ? Yt : Yb;
        const bool stream = (chn == 0);
        const int colp = (warp_n & 1) * 64 + tig * 16;
        #pragma unroll
        for (int mb = 0; mb < 2; mb++) {
            int row0 = base + warp_m * 32 + mb * 16 + g;
            #pragma unroll
            for (int half = 0; half < 2; half++) {
                int r = row0 + half * 8;
                if (r < nRows) {
                    uint4 v0 = make_uint4(
                        h2bits(__floats2half2_rn(acc[mb][0][half*2], acc[mb][0][half*2+1])),
                        h2bits(__floats2half2_rn(acc[mb][1][half*2], acc[mb][1][half*2+1])),
                        h2bits(__floats2half2_rn(acc[mb][2][half*2], acc[mb][2][half*2+1])),
                        h2bits(__floats2half2_rn(acc[mb][3][half*2], acc[mb][3][half*2+1])));
                    uint4 v1 = make_uint4(
                        h2bits(__floats2half2_rn(acc[mb][4][half*2], acc[mb][4][half*2+1])),
                        h2bits(__floats2half2_rn(acc[mb][5][half*2], acc[mb][5][half*2+1])),
                        h2bits(__floats2half2_rn(acc[mb][6][half*2], acc[mb][6][half*2+1])),
                        h2bits(__floats2half2_rn(acc[mb][7][half*2], acc[mb][7][half*2+1])));
                    uint4* p0 = (uint4*)(dst + (size_t)r * 128 + colp);
                    if (stream) { __stcs(p0, v0); __stcs(p0 + 1, v1); }
                    else        { p0[0] = v0;     p0[1] = v1; }
                }
            }
        }

        if (htn < nHT) STOREHT(cur ^ 1);
        __syncthreads();
        cur ^= 1;
        ht = htn;
    }
}

// ---------------- kernel 3: agg1  h1[i] = f16(Yt[i] + mean_d Yb[nbr[i][d]]) ----------------
// Yt read with __ldcs (stream, evict-first) so Yb's 26 MB stays L2-resident.
__global__ void __launch_bounds__(256) agg1_kernel(
    const __half* __restrict__ Yt, const __half* __restrict__ Yb,
    const int* __restrict__ nbr, __half* __restrict__ h1, int N)
{
    int wid = threadIdx.x >> 5, lid = threadIdx.x & 31;
    int node = blockIdx.x * 8 + wid;
    if (node >= N) return;
    const int* nb = nbr + (size_t)node * DEG;
    float a0 = 0.f, a1 = 0.f, a2 = 0.f, a3 = 0.f;
    #pragma unroll
    for (int d = 0; d < DEG; d++) {
        int j = __ldg(nb + d);
        uint2 u = *(const uint2*)(Yb + (size_t)j * 128 + lid * 4);
        float2 f0 = __half22float2(*reinterpret_cast<__half2*>(&u.x));
        float2 f1 = __half22float2(*reinterpret_cast<__half2*>(&u.y));
        a0 += f0.x; a1 += f0.y; a2 += f1.x; a3 += f1.y;
    }
    uint2 t = __ldcs((const uint2*)(Yt + (size_t)node * 128 + lid * 4));
    float2 t0 = __half22float2(*reinterpret_cast<__half2*>(&t.x));
    float2 t1 = __half22float2(*reinterpret_cast<__half2*>(&t.y));
    uint2 o;
    o.x = h2bits(__floats2half2_rn(t0.x + a0 * 0.0625f, t0.y + a1 * 0.0625f));
    o.y = h2bits(__floats2half2_rn(t1.x + a2 * 0.0625f, t1.y + a3 * 0.0625f));
    *(uint2*)(h1 + (size_t)node * 128 + lid * 4) = o;
}

// ---------------- kernel 4: agg2  x2[b] = [h1[nodes[b]], f16(mean(h1[nbr]))] ----------------
__global__ void __launch_bounds__(256) agg2_kernel(
    const __half* __restrict__ h1, const int* __restrict__ nbr,
    const int* __restrict__ nodes, __half* __restrict__ x2, int B)
{
    int wid = threadIdx.x >> 5, lid = threadIdx.x & 31;
    int b = blockIdx.x * 8 + wid;
    if (b >= B) return;
    int self = __ldg(nodes + b);

    uint2 sv = *(const uint2*)(h1 + (size_t)self * 128 + lid * 4);   // bit-copy self half

    const int* nb = nbr + (size_t)self * DEG;
    float a0 = 0.f, a1 = 0.f, a2 = 0.f, a3 = 0.f;
    #pragma unroll
    for (int d = 0; d < DEG; d++) {
        int j = __ldg(nb + d);
        uint2 u = *(const uint2*)(h1 + (size_t)j * 128 + lid * 4);
        float2 f0 = __half22float2(*reinterpret_cast<__half2*>(&u.x));
        float2 f1 = __half22float2(*reinterpret_cast<__half2*>(&u.y));
        a0 += f0.x; a1 += f0.y; a2 += f1.x; a3 += f1.y;
    }
    a0 *= 0.0625f; a1 *= 0.0625f; a2 *= 0.0625f; a3 *= 0.0625f;

    size_t base = (size_t)b * 256;
    *(uint2*)(x2 + base + lid * 4) = sv;
    *(uint2*)(x2 + base + 128 + lid * 4) =
        make_uint2(h2bits(__floats2half2_rn(a0, a1)),
                   h2bits(__floats2half2_rn(a2, a3)));
}

// ---------------- kernel 5: gemm2  out[B,128] = x2[B,256] @ (w2h + w2l) ----------------
// smem: A @ 0 ; B[lvl2] @ A2SLAB + lvl*B2SLAB
__global__ void __launch_bounds__(256, 1) gemm2_kernel(
    const __half* __restrict__ x2, float* __restrict__ out, int B)
{
    extern __shared__ unsigned char smem[];
    const int tid = threadIdx.x, wid = tid >> 5, lid = tid & 31;
    const int g   = lid >> 2, tig = lid & 3;
    const int warp_m = wid & 1, warp_n = wid >> 1;   // 2 x 32 rows, 4 x 32 cols
    const uint32_t smem_base = smem_u32(smem);
    const int base = blockIdx.x * 64;

    const int offA = ((lid & 7) + ((lid >> 3) & 1) * 8) * ROWB2 + (lid >> 4) * 16;
    const int offB = ((lid & 7) + (lid >> 4) * 8) * ROWB2 + ((lid >> 3) & 1) * 16;

    // stage B (both levels, contiguous image)
    {
        const uint4* src = (const uint4*)&g_B2img[0][0];
        uint4* dst = (uint4*)(smem + A2SLAB);
        #pragma unroll 4
        for (int i = tid; i < 2 * B2SLAB / 16; i += 256) dst[i] = src[i];
    }
    // stage A: 64 rows x 512B, pitched to 528
    {
        int r = tid >> 2, q = tid & 3;               // r 0..63, 128B quarter
        int grow = base + r;
        const uint4* sh = (const uint4*)(x2 + (size_t)grow * 256) + q * 8;
        uint4* dh = (uint4*)(smem + r * ROWB2 + q * 128);
        if (grow < B) {
            #pragma unroll
            for (int j = 0; j < 8; j++) dh[j] = sh[j];
        } else {
            uint4 z = make_uint4(0, 0, 0, 0);
            #pragma unroll
            for (int j = 0; j < 8; j++) dh[j] = z;
        }
    }
    __syncthreads();

    float acc[2][4][4];
    #pragma unroll
    for (int mb = 0; mb < 2; mb++)
        #pragma unroll
        for (int nb = 0; nb < 4; nb++)
            #pragma unroll
            for (int q = 0; q < 4; q++) acc[mb][nb][q] = 0.f;

    #pragma unroll
    for (int p = 0; p < 2; p++) {
        const uint32_t Abase = smem_base + warp_m * 32 * ROWB2 + offA;
        const uint32_t Bbase = smem_base + A2SLAB + p * B2SLAB
                             + warp_n * 32 * ROWB2 + offB;
        #pragma unroll
        for (int ks = 0; ks < 16; ks++) {
            const int kB = ks * 32;
            uint32_t a[2][4];
            ldsm4(a[0], Abase + kB);
            ldsm4(a[1], Abase + 16 * ROWB2 + kB);
            uint32_t b[2][4];
            ldsm4(b[0], Bbase + kB);
            ldsm4(b[1], Bbase + 16 * ROWB2 + kB);
            #pragma unroll
            for (int mb = 0; mb < 2; mb++)
                #pragma unroll
                for (int pr = 0; pr < 2; pr++) {
                    mma16816h(acc[mb][pr * 2],     a[mb], &b[pr][0]);
                    mma16816h(acc[mb][pr * 2 + 1], a[mb], &b[pr][2]);
                }
        }
    }

    #pragma unroll
    for (int mb = 0; mb < 2; mb++) {
        int row0 = base + warp_m * 32 + mb * 16 + g;
        #pragma unroll
        for (int nb = 0; nb < 4; nb++) {
            int col = warp_n * 32 + nb * 8 + tig * 2;
            if (row0 < B)
                *(float2*)(out + (size_t)row0 * 128 + col) =
                    make_float2(acc[mb][nb][0], acc[mb][nb][1]);
            if (row0 + 8 < B)
                *(float2*)(out + (size_t)(row0 + 8) * 128 + col) =
                    make_float2(acc[mb][nb][2], acc[mb][nb][3]);
        }
    }
}

// ---------------- host ----------------
extern "C" void kernel_launch(void* const* d_in, const int* in_sizes, int n_in,
                              void* d_out, int out_size)
{
    const float* features     = (const float*)d_in[0];
    const float* w1           = (const float*)d_in[1];
    const float* w2           = (const float*)d_in[2];
    const int*   neighbor_idx = (const int*)d_in[3];
    const int*   nodes        = (const int*)d_in[4];
    float*       out          = (float*)d_out;

    const int N = in_sizes[0] / F;
    const int B = in_sizes[4];

    __half *Yt, *Yb, *h1p, *x2;
    cudaGetSymbolAddress((void**)&Yt,  g_Yt);
    cudaGetSymbolAddress((void**)&Yb,  g_Yb);
    cudaGetSymbolAddress((void**)&h1p, g_h1);
    cudaGetSymbolAddress((void**)&x2,  g_x2);

    // 1) weight images
    prep_kernel<<<256, 256>>>(w1, w2);

    // 2) gemm1: Yt / Yb for all N  (2 CTAs/SM)
    const int nHT = (N + 63) / 64;
    cudaFuncSetAttribute(gemm1_kernel, cudaFuncAttributeMaxDynamicSharedMemorySize, SMEM_G1);
    gemm1_kernel<<<296, 256, SMEM_G1>>>(features, Yt, Yb, N, nHT);

    // 3) agg1 -> h1 (fp16)
    agg1_kernel<<<(N + 7) / 8, 256>>>(Yt, Yb, neighbor_idx, h1p, N);

    // 4) agg2 -> x2 (fp16)
    agg2_kernel<<<(B + 7) / 8, 256>>>(h1p, neighbor_idx, nodes, x2, B);

    // 5) gemm2 -> out
    cudaFuncSetAttribute(gemm2_kernel, cudaFuncAttributeMaxDynamicSharedMemorySize, SMEM_G2);
    gemm2_kernel<<<(B + 63) / 64, 256, SMEM_G2>>>(x2, out, B);
}

// round 13
// speedup vs baseline: 1.0928x; 1.0464x over previous
#include <cuda_runtime.h>
#include <cuda_bf16.h>
#include <cuda_fp16.h>
#include <cstdint>

#define F      128
#define H      128
#define DEG    16
#define KDIM   256
#define NMAX   131072
#define BMAX   16384
#define PITCH  136            // fp16/row gemm1 (K=128); 272 B ≡ 4 words (mod 32) -> conflict-free
#define ROWB   272
#define HSLAB  (64 * ROWB)    // 17408 B  (64-row A half-slab)
#define SLAB   (128 * ROWB)   // 34816 B  (128-n B slab)
#define ABUF_T (2 * HSLAB)    // 34816 B  (A: 2 buffers)
#define SMEM_G1 (ABUF_T + 2 * SLAB)   // 104448 B -> 2 CTAs/SM

#define PITCH2 264            // fp16/row gemm2 (K=256); 528 B ≡ 4 words (mod 32)
#define ROWB2  528
#define A2SLAB (64 * ROWB2)   // 33792 B
#define B2SLAB (128 * ROWB2)  // 67584 B per lvl
#define SMEM_G2 (A2SLAB + 2 * B2SLAB)  // 168960 B

// ---------------- scratch (all intermediates fp16; Yt/Yb/h1/x2 in PERMUTED col layout) ----
__device__ __half g_Yt[(size_t)NMAX * 128];     // f @ w1_top  (streamed, evict-first)
__device__ __half g_Yb[(size_t)NMAX * 128];     // f @ w1_bot  (gathered)
__device__ __half g_h1[(size_t)NMAX * 128];     // layer-1 embeddings
__device__ __half g_B1img[2][128 * PITCH];      // [ch][n][k]   (w1 fp16)
__device__ __half g_B2img[2][128 * PITCH2];     // [lvl][n][p]  (w2 hi/lo fp16, k-rows permuted)
__device__ __half g_x2[(size_t)BMAX * 256];     // layer2 input (fp16)

// ---------------- PTX helpers ----------------
__device__ __forceinline__ void mma16816h(float* c, const uint32_t* a, const uint32_t* b) {
    asm volatile(
        "mma.sync.aligned.m16n8k16.row.col.f32.f16.f16.f32 "
        "{%0,%1,%2,%3}, {%4,%5,%6,%7}, {%8,%9}, {%0,%1,%2,%3};"
        : "+f"(c[0]), "+f"(c[1]), "+f"(c[2]), "+f"(c[3])
        : "r"(a[0]), "r"(a[1]), "r"(a[2]), "r"(a[3]), "r"(b[0]), "r"(b[1]));
}
__device__ __forceinline__ void ldsm4(uint32_t* r, uint32_t addr) {
    asm volatile("ldmatrix.sync.aligned.m8n8.x4.shared.b16 {%0,%1,%2,%3}, [%4];"
        : "=r"(r[0]), "=r"(r[1]), "=r"(r[2]), "=r"(r[3]) : "r"(addr));
}
__device__ __forceinline__ uint32_t smem_u32(const void* p) {
    return (uint32_t)__cvta_generic_to_shared(p);
}
__device__ __forceinline__ void split_fp16(float v, __half& hi, __half& lo) {
    hi = __float2half_rn(v);
    lo = __float2half_rn(v - __half2float(hi));
}
__device__ __forceinline__ uint32_t h2bits(__half2 h) {
    return *reinterpret_cast<uint32_t*>(&h);
}
// PDL intrinsics (griddepcontrol; sm_90+ base ISA)
__device__ __forceinline__ void pdl_wait() {
    asm volatile("griddepcontrol.wait;" ::: "memory");
}
__device__ __forceinline__ void pdl_trigger() {
    asm volatile("griddepcontrol.launch_dependents;" :::);
}

// ---------------- kernel 1: build fp16 weight images ----------------
// w1: B1img[ch][n][k] = f16(w1[ch*128+k][n])
// w2: B2img[lvl][n][p] = split(w2[sigma2(p)][n]) with
//     sigma(p127) = (p127&64) + ((p127>>1)&7)*8 + ((p127>>4)&3)*2 + (p127&1)
__global__ void prep_kernel(const float* __restrict__ w1, const float* __restrict__ w2) {
    int i = blockIdx.x * 256 + threadIdx.x;          // 65536 total
    if (i < 32768) {
        int ch = i >> 14, n = (i >> 7) & 127, k = i & 127;
        float v = w1[(size_t)(ch * 128 + k) * 128 + n];
        g_B1img[ch][n * PITCH + k] = __float2half_rn(v);
    } else if (i < 65536) {
        int j = i - 32768;
        int n = j & 127, p = j >> 7;                 // p = storage k-index 0..255
        int p1  = p & 127;
        int sig = (p1 & 64) + ((p1 >> 1) & 7) * 8 + ((p1 >> 4) & 3) * 2 + (p1 & 1);
        int k   = (p & 128) + sig;
        float v = w2[(size_t)k * 128 + n];
        __half hb, lb;
        split_fp16(v, hb, lb);
        g_B2img[0][n * PITCH2 + p] = hb;
        g_B2img[1][n * PITCH2 + p] = lb;
    }
    pdl_trigger();
}

// ---------------- kernel 2: gemm1  Y[N,256] = f16(f)[N,128] @ f16(w1) ----------------
// Outputs stored fp16 in permuted col layout: storage col = (chunk64) + tig*16 + nb*2 + e.
// smem: A[buf2] @ buf*HSLAB ; B[ch2] @ ABUF_T + ch*SLAB
__global__ void __launch_bounds__(256, 2) gemm1_kernel(
    const float* __restrict__ f, __half* __restrict__ Yt, __half* __restrict__ Yb,
    int nRows, int nHT)
{
    extern __shared__ unsigned char smem[];
    const int tid = threadIdx.x, wid = tid >> 5, lid = tid & 31;
    const int g   = lid >> 2, tig = lid & 3;
    const int warp_m = wid & 1, warp_n = wid >> 1;       // 2 x 32 rows, 4 x 64 cols
    const int chn = warp_n >> 1, ncl = (warp_n & 1) * 64;
    const uint32_t smem_base = smem_u32(smem);

    const int offA = ((lid & 7) + ((lid >> 3) & 1) * 8) * ROWB + (lid >> 4) * 16;
    const int offB = ((lid & 7) + (lid >> 4) * 8) * ROWB + ((lid >> 3) & 1) * 16;

    const int r_st = tid >> 5;          // row in 8-row group
    const int k_st = (tid & 31) * 4;    // k0 elements

    float4 Rst[8];
    auto LOADHT = [&](int ht) {
        const int base = ht * 64;
        #pragma unroll
        for (int j = 0; j < 8; j++) {
            int grow = base + j * 8 + r_st;
            Rst[j] = (grow < nRows) ? *(const float4*)(f + (size_t)grow * 128 + k_st)
                                    : make_float4(0.f, 0.f, 0.f, 0.f);
        }
    };
    auto STOREHT = [&](int buf) {
        unsigned char* Ah = smem + buf * HSLAB;
        #pragma unroll
        for (int j = 0; j < 8; j++) {
            uint2 u;
            u.x = h2bits(__floats2half2_rn(Rst[j].x, Rst[j].y));
            u.y = h2bits(__floats2half2_rn(Rst[j].z, Rst[j].w));
            int r = j * 8 + r_st;
            *(uint2*)(Ah + r * ROWB + k_st * 2) = u;
        }
    };

    // Prologue independent of prep: load first A tile from f.
    int cur = 0;
    int ht = blockIdx.x;
    if (ht < nHT) { LOADHT(ht); STOREHT(0); }

    // Wait for prep's B1img, then stage both B slabs.
    pdl_wait();
    {
        const uint4* src = (const uint4*)&g_B1img[0][0];
        uint4* dst = (uint4*)(smem + ABUF_T);
        #pragma unroll 4
        for (int i = tid; i < 2 * SLAB / 16; i += 256) dst[i] = src[i];
    }
    __syncthreads();

    while (ht < nHT) {
        const int htn  = ht + gridDim.x;
        const int base = ht * 64;

        if (htn < nHT) LOADHT(htn);

        float acc[2][8][4];
        #pragma unroll
        for (int mb = 0; mb < 2; mb++)
            #pragma unroll
            for (int nb = 0; nb < 8; nb++)
                #pragma unroll
                for (int q = 0; q < 4; q++) acc[mb][nb][q] = 0.f;

        const uint32_t Abase = smem_base + cur * HSLAB + warp_m * 32 * ROWB + offA;
        const uint32_t Bbase = smem_base + ABUF_T + chn * SLAB + ncl * ROWB + offB;
        #pragma unroll
        for (int ks = 0; ks < 8; ks++) {
            const int kB = ks * 32;
            uint32_t a[2][4];
            ldsm4(a[0], Abase + kB);
            ldsm4(a[1], Abase + 16 * ROWB + kB);
            uint32_t b[4][4];
            #pragma unroll
            for (int pr = 0; pr < 4; pr++)
                ldsm4(b[pr], Bbase + pr * 16 * ROWB + kB);
            #pragma unroll
            for (int mb = 0; mb < 2; mb++)
                #pragma unroll
                for (int pr = 0; pr < 4; pr++) {
                    mma16816h(acc[mb][pr * 2],     a[mb], &b[pr][0]);
                    mma16816h(acc[mb][pr * 2 + 1], a[mb], &b[pr][2]);
                }
        }

        // permuted epilogue: 16 contiguous halfs per (thread, row) -> 2x STG.128
        __half* dst = (chn == 0) ? Yt : Yb;
        const bool stream = (chn == 0);
        const int colp = (warp_n & 1) * 64 + tig * 16;
        #pragma unroll
        for (int mb = 0; mb < 2; mb++) {
            int row0 = base + warp_m * 32 + mb * 16 + g;
            #pragma unroll
            for (int half = 0; half < 2; half++) {
                int r = row0 + half * 8;
                if (r < nRows) {
                    uint4 v0 = make_uint4(
                        h2bits(__floats2half2_rn(acc[mb][0][half*2], acc[mb][0][half*2+1])),
                        h2bits(__floats2half2_rn(acc[mb][1][half*2], acc[mb][1][half*2+1])),
                        h2bits(__floats2half2_rn(acc[mb][2][half*2], acc[mb][2][half*2+1])),
                        h2bits(__floats2half2_rn(acc[mb][3][half*2], acc[mb][3][half*2+1])));
                    uint4 v1 = make_uint4(
                        h2bits(__floats2half2_rn(acc[mb][4][half*2], acc[mb][4][half*2+1])),
                        h2bits(__floats2half2_rn(acc[mb][5][half*2], acc[mb][5][half*2+1])),
                        h2bits(__floats2half2_rn(acc[mb][6][half*2], acc[mb][6][half*2+1])),
                        h2bits(__floats2half2_rn(acc[mb][7][half*2], acc[mb][7][half*2+1])));
                    uint4* p0 = (uint4*)(dst + (size_t)r * 128 + colp);
                    if (stream) { __stcs(p0, v0); __stcs(p0 + 1, v1); }
                    else        { p0[0] = v0;     p0[1] = v1; }
                }
            }
        }

        if (htn < nHT) STOREHT(cur ^ 1);
        __syncthreads();
        cur ^= 1;
        ht = htn;
    }
    pdl_trigger();
}

// ---------------- kernel 3: agg1  h1[i] = f16(Yt[i] + mean_d Yb[nbr[i][d]]) ----------------
__global__ void __launch_bounds__(256) agg1_kernel(
    const __half* __restrict__ Yt, const __half* __restrict__ Yb,
    const int* __restrict__ nbr, __half* __restrict__ h1, int N)
{
    int wid = threadIdx.x >> 5, lid = threadIdx.x & 31;
    int node = blockIdx.x * 8 + wid;
    if (node >= N) { pdl_wait(); pdl_trigger(); return; }
    // prologue independent of gemm1: neighbor indices
    const int* nb = nbr + (size_t)node * DEG;
    int idx[DEG];
    #pragma unroll
    for (int d = 0; d < DEG; d++) idx[d] = __ldg(nb + d);

    pdl_wait();   // Yt/Yb ready

    float a0 = 0.f, a1 = 0.f, a2 = 0.f, a3 = 0.f;
    #pragma unroll
    for (int d = 0; d < DEG; d++) {
        uint2 u = *(const uint2*)(Yb + (size_t)idx[d] * 128 + lid * 4);
        float2 f0 = __half22float2(*reinterpret_cast<__half2*>(&u.x));
        float2 f1 = __half22float2(*reinterpret_cast<__half2*>(&u.y));
        a0 += f0.x; a1 += f0.y; a2 += f1.x; a3 += f1.y;
    }
    uint2 t = __ldcs((const uint2*)(Yt + (size_t)node * 128 + lid * 4));
    float2 t0 = __half22float2(*reinterpret_cast<__half2*>(&t.x));
    float2 t1 = __half22float2(*reinterpret_cast<__half2*>(&t.y));
    uint2 o;
    o.x = h2bits(__floats2half2_rn(t0.x + a0 * 0.0625f, t0.y + a1 * 0.0625f));
    o.y = h2bits(__floats2half2_rn(t1.x + a2 * 0.0625f, t1.y + a3 * 0.0625f));
    *(uint2*)(h1 + (size_t)node * 128 + lid * 4) = o;
    pdl_trigger();
}

// ---------------- kernel 4: agg2  x2[b] = [h1[nodes[b]], f16(mean(h1[nbr]))] ----------------
__global__ void __launch_bounds__(256) agg2_kernel(
    const __half* __restrict__ h1, const int* __restrict__ nbr,
    const int* __restrict__ nodes, __half* __restrict__ x2, int B)
{
    int wid = threadIdx.x >> 5, lid = threadIdx.x & 31;
    int b = blockIdx.x * 8 + wid;
    if (b >= B) { pdl_wait(); pdl_trigger(); return; }
    // prologue independent of agg1: self + neighbor indices
    int self = __ldg(nodes + b);
    const int* nb = nbr + (size_t)self * DEG;
    int idx[DEG];
    #pragma unroll
    for (int d = 0; d < DEG; d++) idx[d] = __ldg(nb + d);

    pdl_wait();   // h1 ready

    uint2 sv = *(const uint2*)(h1 + (size_t)self * 128 + lid * 4);   // bit-copy self half

    float a0 = 0.f, a1 = 0.f, a2 = 0.f, a3 = 0.f;
    #pragma unroll
    for (int d = 0; d < DEG; d++) {
        uint2 u = *(const uint2*)(h1 + (size_t)idx[d] * 128 + lid * 4);
        float2 f0 = __half22float2(*reinterpret_cast<__half2*>(&u.x));
        float2 f1 = __half22float2(*reinterpret_cast<__half2*>(&u.y));
        a0 += f0.x; a1 += f0.y; a2 += f1.x; a3 += f1.y;
    }
    a0 *= 0.0625f; a1 *= 0.0625f; a2 *= 0.0625f; a3 *= 0.0625f;

    size_t base = (size_t)b * 256;
    *(uint2*)(x2 + base + lid * 4) = sv;
    *(uint2*)(x2 + base + 128 + lid * 4) =
        make_uint2(h2bits(__floats2half2_rn(a0, a1)),
                   h2bits(__floats2half2_rn(a2, a3)));
    pdl_trigger();
}

// ---------------- kernel 5: gemm2  out[B,128] = x2[B,256] @ (w2h + w2l) ----------------
// smem: A @ 0 ; B[lvl2] @ A2SLAB + lvl*B2SLAB
__global__ void __launch_bounds__(256, 1) gemm2_kernel(
    const __half* __restrict__ x2, float* __restrict__ out, int B)
{
    extern __shared__ unsigned char smem[];
    const int tid = threadIdx.x, wid = tid >> 5, lid = tid & 31;
    const int g   = lid >> 2, tig = lid & 3;
    const int warp_m = wid & 1, warp_n = wid >> 1;   // 2 x 32 rows, 4 x 32 cols
    const uint32_t smem_base = smem_u32(smem);
    const int base = blockIdx.x * 64;

    const int offA = ((lid & 7) + ((lid >> 3) & 1) * 8) * ROWB2 + (lid >> 4) * 16;
    const int offB = ((lid & 7) + (lid >> 4) * 8) * ROWB2 + ((lid >> 3) & 1) * 16;

    // prologue independent of agg2: stage B (prep output) — overlaps agg2's tail
    {
        const uint4* src = (const uint4*)&g_B2img[0][0];
        uint4* dst = (uint4*)(smem + A2SLAB);
        #pragma unroll 4
        for (int i = tid; i < 2 * B2SLAB / 16; i += 256) dst[i] = src[i];
    }

    pdl_wait();   // x2 ready

    // stage A: 64 rows x 512B, pitched to 528
    {
        int r = tid >> 2, q = tid & 3;               // r 0..63, 128B quarter
        int grow = base + r;
        const uint4* sh = (const uint4*)(x2 + (size_t)grow * 256) + q * 8;
        uint4* dh = (uint4*)(smem + r * ROWB2 + q * 128);
        if (grow < B) {
            #pragma unroll
            for (int j = 0; j < 8; j++) dh[j] = sh[j];
        } else {
            uint4 z = make_uint4(0, 0, 0, 0);
            #pragma unroll
            for (int j = 0; j < 8; j++) dh[j] = z;
        }
    }
    __syncthreads();

    float acc[2][4][4];
    #pragma unroll
    for (int mb = 0; mb < 2; mb++)
        #pragma unroll
        for (int nb = 0; nb < 4; nb++)
            #pragma unroll
            for (int q = 0; q < 4; q++) acc[mb][nb][q] = 0.f;

    #pragma unroll
    for (int p = 0; p < 2; p++) {
        const uint32_t Abase = smem_base + warp_m * 32 * ROWB2 + offA;
        const uint32_t Bbase = smem_base + A2SLAB + p * B2SLAB
                             + warp_n * 32 * ROWB2 + offB;
        #pragma unroll
        for (int ks = 0; ks < 16; ks++) {
            const int kB = ks * 32;
            uint32_t a[2][4];
            ldsm4(a[0], Abase + kB);
            ldsm4(a[1], Abase + 16 * ROWB2 + kB);
            uint32_t b[2][4];
            ldsm4(b[0], Bbase + kB);
            ldsm4(b[1], Bbase + 16 * ROWB2 + kB);
            #pragma unroll
            for (int mb = 0; mb < 2; mb++)
                #pragma unroll
                for (int pr = 0; pr < 2; pr++) {
                    mma16816h(acc[mb][pr * 2],     a[mb], &b[pr][0]);
                    mma16816h(acc[mb][pr * 2 + 1], a[mb], &b[pr][2]);
                }
        }
    }

    #pragma unroll
    for (int mb = 0; mb < 2; mb++) {
        int row0 = base + warp_m * 32 + mb * 16 + g;
        #pragma unroll
        for (int nb = 0; nb < 4; nb++) {
            int col = warp_n * 32 + nb * 8 + tig * 2;
            if (row0 < B)
                *(float2*)(out + (size_t)row0 * 128 + col) =
                    make_float2(acc[mb][nb][0], acc[mb][nb][1]);
            if (row0 + 8 < B)
                *(float2*)(out + (size_t)(row0 + 8) * 128 + col) =
                    make_float2(acc[mb][nb][2], acc[mb][nb][3]);
        }
    }
}

// ---------------- host ----------------
static void launch_pdl(void* fn, dim3 grid, dim3 block, size_t smem, void** args) {
    cudaLaunchConfig_t cfg = {};
    cfg.gridDim = grid;
    cfg.blockDim = block;
    cfg.dynamicSmemBytes = smem;
    cfg.stream = 0;
    cudaLaunchAttribute attr[1];
    attr[0].id = cudaLaunchAttributeProgrammaticStreamSerialization;
    attr[0].val.programmaticStreamSerializationAllowed = 1;
    cfg.attrs = attr;
    cfg.numAttrs = 1;
    cudaLaunchKernelExC(&cfg, fn, args);
}

extern "C" void kernel_launch(void* const* d_in, const int* in_sizes, int n_in,
                              void* d_out, int out_size)
{
    const float* features     = (const float*)d_in[0];
    const float* w1           = (const float*)d_in[1];
    const float* w2           = (const float*)d_in[2];
    const int*   neighbor_idx = (const int*)d_in[3];
    const int*   nodes        = (const int*)d_in[4];
    float*       out          = (float*)d_out;

    const int N = in_sizes[0] / F;
    const int B = in_sizes[4];

    __half *Yt, *Yb, *h1p, *x2;
    cudaGetSymbolAddress((void**)&Yt,  g_Yt);
    cudaGetSymbolAddress((void**)&Yb,  g_Yb);
    cudaGetSymbolAddress((void**)&h1p, g_h1);
    cudaGetSymbolAddress((void**)&x2,  g_x2);

    cudaFuncSetAttribute(gemm1_kernel, cudaFuncAttributeMaxDynamicSharedMemorySize, SMEM_G1);
    cudaFuncSetAttribute(gemm2_kernel, cudaFuncAttributeMaxDynamicSharedMemorySize, SMEM_G2);

    // 1) weight images (no PDL attr; it is the root)
    prep_kernel<<<256, 256>>>(w1, w2);

    // 2) gemm1 (PDL: overlaps its A-tile prologue with prep)
    int nHT = (N + 63) / 64;
    {
        void* args[] = { (void*)&features, (void*)&Yt, (void*)&Yb, (void*)&N, (void*)&nHT };
        launch_pdl((void*)gemm1_kernel, dim3(296), dim3(256), SMEM_G1, args);
    }
    // 3) agg1 (PDL: index loads overlap gemm1 drain)
    {
        int grid = (N + 7) / 8;
        void* args[] = { (void*)&Yt, (void*)&Yb, (void*)&neighbor_idx, (void*)&h1p, (void*)&N };
        launch_pdl((void*)agg1_kernel, dim3(grid), dim3(256), 0, args);
    }
    // 4) agg2 (PDL)
    {
        int grid = (B + 7) / 8;
        void* args[] = { (void*)&h1p, (void*)&neighbor_idx, (void*)&nodes, (void*)&x2, (void*)&B };
        launch_pdl((void*)agg2_kernel, dim3(grid), dim3(256), 0, args);
    }
    // 5) gemm2 (PDL: B staging overlaps agg2)
    {
        int grid = (B + 63) / 64;
        void* args[] = { (void*)&x2, (void*)&out, (void*)&B };
        launch_pdl((void*)gemm2_kernel, dim3(grid), dim3(256), SMEM_G2, args);
    }
}

// round 14
// speedup vs baseline: 1.1118x; 1.0174x over previous
#include <cuda_runtime.h>
#include <cuda_bf16.h>
#include <cuda_fp16.h>
#include <cstdint>

#define F      128
#define H      128
#define DEG    16
#define KDIM   256
#define NMAX   131072
#define BMAX   16384
#define PITCH  136            // fp16/row gemm1 (K=128); 272 B ≡ 4 words (mod 32) -> conflict-free
#define ROWB   272
#define HSLAB  (64 * ROWB)    // 17408 B  (64-row A half-slab)
#define SLAB   (128 * ROWB)   // 34816 B  (128-n B slab)
#define ABUF_T (2 * HSLAB)    // 34816 B  (A: 2 buffers)
#define SMEM_G1 (ABUF_T + 2 * SLAB)   // 104448 B -> 2 CTAs/SM

#define PITCH2 264            // fp16/row gemm2 (K=256); 528 B ≡ 4 words (mod 32)
#define ROWB2  528
#define A2SLAB (64 * ROWB2)   // 33792 B
#define B2SLAB (128 * ROWB2)  // 67584 B per lvl
#define SMEM_G2 (A2SLAB + 2 * B2SLAB)  // 168960 B

// ---------------- scratch (all intermediates fp16; Yt/Yb/h1/x2 in PERMUTED col layout) ----
__device__ __half g_Yt[(size_t)NMAX * 128];     // f @ w1_top  (streamed, evict-first)
__device__ __half g_Yb[(size_t)NMAX * 128];     // f @ w1_bot  (gathered)
__device__ __half g_h1[(size_t)NMAX * 128];     // layer-1 embeddings
__device__ __half g_B1img[2][128 * PITCH];      // [ch][n][k]   (w1 fp16)
__device__ __half g_B2img[2][128 * PITCH2];     // [lvl][n][p]  (w2 hi/lo fp16, k-rows permuted)
__device__ __half g_x2[(size_t)BMAX * 256];     // layer2 input (fp16)

// ---------------- PTX helpers ----------------
__device__ __forceinline__ void mma16816h(float* c, const uint32_t* a, const uint32_t* b) {
    asm volatile(
        "mma.sync.aligned.m16n8k16.row.col.f32.f16.f16.f32 "
        "{%0,%1,%2,%3}, {%4,%5,%6,%7}, {%8,%9}, {%0,%1,%2,%3};"
        : "+f"(c[0]), "+f"(c[1]), "+f"(c[2]), "+f"(c[3])
        : "r"(a[0]), "r"(a[1]), "r"(a[2]), "r"(a[3]), "r"(b[0]), "r"(b[1]));
}
__device__ __forceinline__ void ldsm4(uint32_t* r, uint32_t addr) {
    asm volatile("ldmatrix.sync.aligned.m8n8.x4.shared.b16 {%0,%1,%2,%3}, [%4];"
        : "=r"(r[0]), "=r"(r[1]), "=r"(r[2]), "=r"(r[3]) : "r"(addr));
}
__device__ __forceinline__ uint32_t smem_u32(const void* p) {
    return (uint32_t)__cvta_generic_to_shared(p);
}
__device__ __forceinline__ void split_fp16(float v, __half& hi, __half& lo) {
    hi = __float2half_rn(v);
    lo = __float2half_rn(v - __half2float(hi));
}
__device__ __forceinline__ uint32_t h2bits(__half2 h) {
    return *reinterpret_cast<uint32_t*>(&h);
}
// PDL intrinsics (griddepcontrol; sm_90+ base ISA)
__device__ __forceinline__ void pdl_wait() {
    asm volatile("griddepcontrol.wait;" ::: "memory");
}
__device__ __forceinline__ void pdl_trigger() {
    asm volatile("griddepcontrol.launch_dependents;" :::);
}
// accumulate 8 fp16 (uint4) into 8 fp32
__device__ __forceinline__ void acc8(float* a, uint4 u) {
    float2 p0 = __half22float2(*reinterpret_cast<__half2*>(&u.x));
    float2 p1 = __half22float2(*reinterpret_cast<__half2*>(&u.y));
    float2 p2 = __half22float2(*reinterpret_cast<__half2*>(&u.z));
    float2 p3 = __half22float2(*reinterpret_cast<__half2*>(&u.w));
    a[0] += p0.x; a[1] += p0.y; a[2] += p1.x; a[3] += p1.y;
    a[4] += p2.x; a[5] += p2.y; a[6] += p3.x; a[7] += p3.y;
}

// ---------------- kernel 1: build fp16 weight images ----------------
// w1: B1img[ch][n][k] = f16(w1[ch*128+k][n])
// w2: B2img[lvl][n][p] = split(w2[sigma2(p)][n]) with
//     sigma(p127) = (p127&64) + ((p127>>1)&7)*8 + ((p127>>4)&3)*2 + (p127&1)
__global__ void prep_kernel(const float* __restrict__ w1, const float* __restrict__ w2) {
    int i = blockIdx.x * 256 + threadIdx.x;          // 65536 total
    if (i < 32768) {
        int ch = i >> 14, n = (i >> 7) & 127, k = i & 127;
        float v = w1[(size_t)(ch * 128 + k) * 128 + n];
        g_B1img[ch][n * PITCH + k] = __float2half_rn(v);
    } else if (i < 65536) {
        int j = i - 32768;
        int n = j & 127, p = j >> 7;                 // p = storage k-index 0..255
        int p1  = p & 127;
        int sig = (p1 & 64) + ((p1 >> 1) & 7) * 8 + ((p1 >> 4) & 3) * 2 + (p1 & 1);
        int k   = (p & 128) + sig;
        float v = w2[(size_t)k * 128 + n];
        __half hb, lb;
        split_fp16(v, hb, lb);
        g_B2img[0][n * PITCH2 + p] = hb;
        g_B2img[1][n * PITCH2 + p] = lb;
    }
    pdl_trigger();
}

// ---------------- kernel 2: gemm1  Y[N,256] = f16(f)[N,128] @ f16(w1) ----------------
// Outputs stored fp16 in permuted col layout: storage col = (chunk64) + tig*16 + nb*2 + e.
// smem: A[buf2] @ buf*HSLAB ; B[ch2] @ ABUF_T + ch*SLAB
__global__ void __launch_bounds__(256, 2) gemm1_kernel(
    const float* __restrict__ f, __half* __restrict__ Yt, __half* __restrict__ Yb,
    int nRows, int nHT)
{
    extern __shared__ unsigned char smem[];
    const int tid = threadIdx.x, wid = tid >> 5, lid = tid & 31;
    const int g   = lid >> 2, tig = lid & 3;
    const int warp_m = wid & 1, warp_n = wid >> 1;       // 2 x 32 rows, 4 x 64 cols
    const int chn = warp_n >> 1, ncl = (warp_n & 1) * 64;
    const uint32_t smem_base = smem_u32(smem);

    const int offA = ((lid & 7) + ((lid >> 3) & 1) * 8) * ROWB + (lid >> 4) * 16;
    const int offB = ((lid & 7) + (lid >> 4) * 8) * ROWB + ((lid >> 3) & 1) * 16;

    const int r_st = tid >> 5;          // row in 8-row group
    const int k_st = (tid & 31) * 4;    // k0 elements

    float4 Rst[8];
    auto LOADHT = [&](int ht) {
        const int base = ht * 64;
        #pragma unroll
        for (int j = 0; j < 8; j++) {
            int grow = base + j * 8 + r_st;
            Rst[j] = (grow < nRows) ? *(const float4*)(f + (size_t)grow * 128 + k_st)
                                    : make_float4(0.f, 0.f, 0.f, 0.f);
        }
    };
    auto STOREHT = [&](int buf) {
        unsigned char* Ah = smem + buf * HSLAB;
        #pragma unroll
        for (int j = 0; j < 8; j++) {
            uint2 u;
            u.x = h2bits(__floats2half2_rn(Rst[j].x, Rst[j].y));
            u.y = h2bits(__floats2half2_rn(Rst[j].z, Rst[j].w));
            int r = j * 8 + r_st;
            *(uint2*)(Ah + r * ROWB + k_st * 2) = u;
        }
    };

    // Prologue independent of prep: load first A tile from f.
    int cur = 0;
    int ht = blockIdx.x;
    if (ht < nHT) { LOADHT(ht); STOREHT(0); }

    // Wait for prep's B1img, then stage both B slabs.
    pdl_wait();
    {
        const uint4* src = (const uint4*)&g_B1img[0][0];
        uint4* dst = (uint4*)(smem + ABUF_T);
        #pragma unroll 4
        for (int i = tid; i < 2 * SLAB / 16; i += 256) dst[i] = src[i];
    }
    __syncthreads();

    while (ht < nHT) {
        const int htn  = ht + gridDim.x;
        const int base = ht * 64;

        if (htn < nHT) LOADHT(htn);

        float acc[2][8][4];
        #pragma unroll
        for (int mb = 0; mb < 2; mb++)
            #pragma unroll
            for (int nb = 0; nb < 8; nb++)
                #pragma unroll
                for (int q = 0; q < 4; q++) acc[mb][nb][q] = 0.f;

        const uint32_t Abase = smem_base + cur * HSLAB + warp_m * 32 * ROWB + offA;
        const uint32_t Bbase = smem_base + ABUF_T + chn * SLAB + ncl * ROWB + offB;
        #pragma unroll
        for (int ks = 0; ks < 8; ks++) {
            const int kB = ks * 32;
            uint32_t a[2][4];
            ldsm4(a[0], Abase + kB);
            ldsm4(a[1], Abase + 16 * ROWB + kB);
            uint32_t b[4][4];
            #pragma unroll
            for (int pr = 0; pr < 4; pr++)
                ldsm4(b[pr], Bbase + pr * 16 * ROWB + kB);
            #pragma unroll
            for (int mb = 0; mb < 2; mb++)
                #pragma unroll
                for (int pr = 0; pr < 4; pr++) {
                    mma16816h(acc[mb][pr * 2],     a[mb], &b[pr][0]);
                    mma16816h(acc[mb][pr * 2 + 1], a[mb], &b[pr][2]);
                }
        }

        // permuted epilogue: 16 contiguous halfs per (thread, row) -> 2x STG.128
        __half* dst = (chn == 0) ? Yt : Yb;
        const bool stream = (chn == 0);
        const int colp = (warp_n & 1) * 64 + tig * 16;
        #pragma unroll
        for (int mb = 0; mb < 2; mb++) {
            int row0 = base + warp_m * 32 + mb * 16 + g;
            #pragma unroll
            for (int half = 0; half < 2; half++) {
                int r = row0 + half * 8;
                if (r < nRows) {
                    uint4 v0 = make_uint4(
                        h2bits(__floats2half2_rn(acc[mb][0][half*2], acc[mb][0][half*2+1])),
                        h2bits(__floats2half2_rn(acc[mb][1][half*2], acc[mb][1][half*2+1])),
                        h2bits(__floats2half2_rn(acc[mb][2][half*2], acc[mb][2][half*2+1])),
                        h2bits(__floats2half2_rn(acc[mb][3][half*2], acc[mb][3][half*2+1])));
                    uint4 v1 = make_uint4(
                        h2bits(__floats2half2_rn(acc[mb][4][half*2], acc[mb][4][half*2+1])),
                        h2bits(__floats2half2_rn(acc[mb][5][half*2], acc[mb][5][half*2+1])),
                        h2bits(__floats2half2_rn(acc[mb][6][half*2], acc[mb][6][half*2+1])),
                        h2bits(__floats2half2_rn(acc[mb][7][half*2], acc[mb][7][half*2+1])));
                    uint4* p0 = (uint4*)(dst + (size_t)r * 128 + colp);
                    if (stream) { __stcs(p0, v0); __stcs(p0 + 1, v1); }
                    else        { p0[0] = v0;     p0[1] = v1; }
                }
            }
        }

        if (htn < nHT) STOREHT(cur ^ 1);
        __syncthreads();
        cur ^= 1;
        ht = htn;
    }
    pdl_trigger();
}

// ---------------- kernel 3: agg1  h1[i] = f16(Yt[i] + mean_d Yb[nbr[i][d]]) ----------------
// 2 nodes per warp; half-warp h gathers neighbor subset {2d+h}; uint4 (16B) loads;
// shfl_xor(16) combines halves; each half then finalizes one node in parallel.
__global__ void __launch_bounds__(256) agg1_kernel(
    const __half* __restrict__ Yt, const __half* __restrict__ Yb,
    const int* __restrict__ nbr, __half* __restrict__ h1, int N)
{
    int wid = threadIdx.x >> 5, lid = threadIdx.x & 31;
    int c = lid & 15, h = lid >> 4;
    int node0 = (blockIdx.x * 8 + wid) * 2;
    if (node0 >= N) { pdl_wait(); pdl_trigger(); return; }
    int node1 = node0 + 1;
    bool has1 = node1 < N;

    // prologue independent of gemm1: neighbor indices (h-th subset of each node)
    const int* nb0 = nbr + (size_t)node0 * DEG;
    const int* nb1 = nbr + (size_t)(has1 ? node1 : node0) * DEG;
    int idxA[8], idxB[8];
    #pragma unroll
    for (int d = 0; d < 8; d++) {
        idxA[d] = __ldg(nb0 + 2 * d + h);
        idxB[d] = __ldg(nb1 + 2 * d + h);
    }

    pdl_wait();   // Yt/Yb ready

    float a0[8], a1[8];
    #pragma unroll
    for (int q = 0; q < 8; q++) { a0[q] = 0.f; a1[q] = 0.f; }
    #pragma unroll
    for (int d = 0; d < 8; d++) {
        uint4 uA = *(const uint4*)(Yb + (size_t)idxA[d] * 128 + c * 8);
        uint4 uB = *(const uint4*)(Yb + (size_t)idxB[d] * 128 + c * 8);
        acc8(a0, uA);
        acc8(a1, uB);
    }
    // combine the two halves' partial sums
    #pragma unroll
    for (int q = 0; q < 8; q++) {
        a0[q] += __shfl_xor_sync(0xFFFFFFFFu, a0[q], 16);
        a1[q] += __shfl_xor_sync(0xFFFFFFFFu, a1[q], 16);
    }
    // half 0 finalizes node0, half 1 finalizes node1 (both have full sums)
    int mynode = h ? node1 : node0;
    float* ma = h ? a1 : a0;
    if (mynode < N) {
        uint4 t = __ldcs((const uint4*)(Yt + (size_t)mynode * 128 + c * 8));
        float2 t0 = __half22float2(*reinterpret_cast<__half2*>(&t.x));
        float2 t1 = __half22float2(*reinterpret_cast<__half2*>(&t.y));
        float2 t2 = __half22float2(*reinterpret_cast<__half2*>(&t.z));
        float2 t3 = __half22float2(*reinterpret_cast<__half2*>(&t.w));
        uint4 o;
        o.x = h2bits(__floats2half2_rn(t0.x + ma[0] * 0.0625f, t0.y + ma[1] * 0.0625f));
        o.y = h2bits(__floats2half2_rn(t1.x + ma[2] * 0.0625f, t1.y + ma[3] * 0.0625f));
        o.z = h2bits(__floats2half2_rn(t2.x + ma[4] * 0.0625f, t2.y + ma[5] * 0.0625f));
        o.w = h2bits(__floats2half2_rn(t3.x + ma[6] * 0.0625f, t3.y + ma[7] * 0.0625f));
        *(uint4*)(h1 + (size_t)mynode * 128 + c * 8) = o;
    }
    pdl_trigger();
}

// ---------------- kernel 4: agg2  x2[b] = [h1[nodes[b]], f16(mean(h1[nbr]))] ----------------
// 1 row per warp; half-warp split over neighbors; uint4 loads; shfl combine.
__global__ void __launch_bounds__(256) agg2_kernel(
    const __half* __restrict__ h1, const int* __restrict__ nbr,
    const int* __restrict__ nodes, __half* __restrict__ x2, int B)
{
    int wid = threadIdx.x >> 5, lid = threadIdx.x & 31;
    int c = lid & 15, h = lid >> 4;
    int b = blockIdx.x * 8 + wid;
    if (b >= B) { pdl_wait(); pdl_trigger(); return; }
    // prologue independent of agg1: self + neighbor indices
    int self = __ldg(nodes + b);
    const int* nb = nbr + (size_t)self * DEG;
    int idx[8];
    #pragma unroll
    for (int d = 0; d < 8; d++) idx[d] = __ldg(nb + 2 * d + h);

    pdl_wait();   // h1 ready

    float a[8];
    #pragma unroll
    for (int q = 0; q < 8; q++) a[q] = 0.f;
    #pragma unroll
    for (int d = 0; d < 8; d++) {
        uint4 u = *(const uint4*)(h1 + (size_t)idx[d] * 128 + c * 8);
        acc8(a, u);
    }
    #pragma unroll
    for (int q = 0; q < 8; q++)
        a[q] += __shfl_xor_sync(0xFFFFFFFFu, a[q], 16);

    size_t base = (size_t)b * 256;
    if (h == 0) {
        // self half: straight fp16 bit-copy (16 lanes x 16B = 256B)
        uint4 sv = *(const uint4*)(h1 + (size_t)self * 128 + c * 8);
        *(uint4*)(x2 + base + c * 8) = sv;
    } else {
        // mean half
        uint4 o;
        o.x = h2bits(__floats2half2_rn(a[0] * 0.0625f, a[1] * 0.0625f));
        o.y = h2bits(__floats2half2_rn(a[2] * 0.0625f, a[3] * 0.0625f));
        o.z = h2bits(__floats2half2_rn(a[4] * 0.0625f, a[5] * 0.0625f));
        o.w = h2bits(__floats2half2_rn(a[6] * 0.0625f, a[7] * 0.0625f));
        *(uint4*)(x2 + base + 128 + c * 8) = o;
    }
    pdl_trigger();
}

// ---------------- kernel 5: gemm2  out[B,128] = x2[B,256] @ (w2h + w2l) ----------------
// smem: A @ 0 ; B[lvl2] @ A2SLAB + lvl*B2SLAB
__global__ void __launch_bounds__(256, 1) gemm2_kernel(
    const __half* __restrict__ x2, float* __restrict__ out, int B)
{
    extern __shared__ unsigned char smem[];
    const int tid = threadIdx.x, wid = tid >> 5, lid = tid & 31;
    const int g   = lid >> 2, tig = lid & 3;
    const int warp_m = wid & 1, warp_n = wid >> 1;   // 2 x 32 rows, 4 x 32 cols
    const uint32_t smem_base = smem_u32(smem);
    const int base = blockIdx.x * 64;

    const int offA = ((lid & 7) + ((lid >> 3) & 1) * 8) * ROWB2 + (lid >> 4) * 16;
    const int offB = ((lid & 7) + (lid >> 4) * 8) * ROWB2 + ((lid >> 3) & 1) * 16;

    // prologue independent of agg2: stage B (prep output) — overlaps agg2's tail
    {
        const uint4* src = (const uint4*)&g_B2img[0][0];
        uint4* dst = (uint4*)(smem + A2SLAB);
        #pragma unroll 4
        for (int i = tid; i < 2 * B2SLAB / 16; i += 256) dst[i] = src[i];
    }

    pdl_wait();   // x2 ready

    // stage A: 64 rows x 512B, pitched to 528
    {
        int r = tid >> 2, q = tid & 3;               // r 0..63, 128B quarter
        int grow = base + r;
        const uint4* sh = (const uint4*)(x2 + (size_t)grow * 256) + q * 8;
        uint4* dh = (uint4*)(smem + r * ROWB2 + q * 128);
        if (grow < B) {
            #pragma unroll
            for (int j = 0; j < 8; j++) dh[j] = sh[j];
        } else {
            uint4 z = make_uint4(0, 0, 0, 0);
            #pragma unroll
            for (int j = 0; j < 8; j++) dh[j] = z;
        }
    }
    __syncthreads();

    float acc[2][4][4];
    #pragma unroll
    for (int mb = 0; mb < 2; mb++)
        #pragma unroll
        for (int nb = 0; nb < 4; nb++)
            #pragma unroll
            for (int q = 0; q < 4; q++) acc[mb][nb][q] = 0.f;

    #pragma unroll
    for (int p = 0; p < 2; p++) {
        const uint32_t Abase = smem_base + warp_m * 32 * ROWB2 + offA;
        const uint32_t Bbase = smem_base + A2SLAB + p * B2SLAB
                             + warp_n * 32 * ROWB2 + offB;
        #pragma unroll
        for (int ks = 0; ks < 16; ks++) {
            const int kB = ks * 32;
            uint32_t a[2][4];
            ldsm4(a[0], Abase + kB);
            ldsm4(a[1], Abase + 16 * ROWB2 + kB);
            uint32_t b[2][4];
            ldsm4(b[0], Bbase + kB);
            ldsm4(b[1], Bbase + 16 * ROWB2 + kB);
            #pragma unroll
            for (int mb = 0; mb < 2; mb++)
                #pragma unroll
                for (int pr = 0; pr < 2; pr++) {
                    mma16816h(acc[mb][pr * 2],     a[mb], &b[pr][0]);
                    mma16816h(acc[mb][pr * 2 + 1], a[mb], &b[pr][2]);
                }
        }
    }

    #pragma unroll
    for (int mb = 0; mb < 2; mb++) {
        int row0 = base + warp_m * 32 + mb * 16 + g;
        #pragma unroll
        for (int nb = 0; nb < 4; nb++) {
            int col = warp_n * 32 + nb * 8 + tig * 2;
            if (row0 < B)
                *(float2*)(out + (size_t)row0 * 128 + col) =
                    make_float2(acc[mb][nb][0], acc[mb][nb][1]);
            if (row0 + 8 < B)
                *(float2*)(out + (size_t)(row0 + 8) * 128 + col) =
                    make_float2(acc[mb][nb][2], acc[mb][nb][3]);
        }
    }
}

// ---------------- host ----------------
static void launch_pdl(void* fn, dim3 grid, dim3 block, size_t smem, void** args) {
    cudaLaunchConfig_t cfg = {};
    cfg.gridDim = grid;
    cfg.blockDim = block;
    cfg.dynamicSmemBytes = smem;
    cfg.stream = 0;
    cudaLaunchAttribute attr[1];
    attr[0].id = cudaLaunchAttributeProgrammaticStreamSerialization;
    attr[0].val.programmaticStreamSerializationAllowed = 1;
    cfg.attrs = attr;
    cfg.numAttrs = 1;
    cudaLaunchKernelExC(&cfg, fn, args);
}

extern "C" void kernel_launch(void* const* d_in, const int* in_sizes, int n_in,
                              void* d_out, int out_size)
{
    const float* features     = (const float*)d_in[0];
    const float* w1           = (const float*)d_in[1];
    const float* w2           = (const float*)d_in[2];
    const int*   neighbor_idx = (const int*)d_in[3];
    const int*   nodes        = (const int*)d_in[4];
    float*       out          = (float*)d_out;

    const int N = in_sizes[0] / F;
    const int B = in_sizes[4];

    __half *Yt, *Yb, *h1p, *x2;
    cudaGetSymbolAddress((void**)&Yt,  g_Yt);
    cudaGetSymbolAddress((void**)&Yb,  g_Yb);
    cudaGetSymbolAddress((void**)&h1p, g_h1);
    cudaGetSymbolAddress((void**)&x2,  g_x2);

    cudaFuncSetAttribute(gemm1_kernel, cudaFuncAttributeMaxDynamicSharedMemorySize, SMEM_G1);
    cudaFuncSetAttribute(gemm2_kernel, cudaFuncAttributeMaxDynamicSharedMemorySize, SMEM_G2);

    // 1) weight images (no PDL attr; it is the root)
    prep_kernel<<<256, 256>>>(w1, w2);

    // 2) gemm1 (PDL: overlaps its A-tile prologue with prep)
    int nHT = (N + 63) / 64;
    {
        void* args[] = { (void*)&features, (void*)&Yt, (void*)&Yb, (void*)&N, (void*)&nHT };
        launch_pdl((void*)gemm1_kernel, dim3(296), dim3(256), SMEM_G1, args);
    }
    // 3) agg1 (PDL; 2 nodes/warp)
    {
        int grid = (N + 15) / 16;
        void* args[] = { (void*)&Yt, (void*)&Yb, (void*)&neighbor_idx, (void*)&h1p, (void*)&N };
        launch_pdl((void*)agg1_kernel, dim3(grid), dim3(256), 0, args);
    }
    // 4) agg2 (PDL)
    {
        int grid = (B + 7) / 8;
        void* args[] = { (void*)&h1p, (void*)&neighbor_idx, (void*)&nodes, (void*)&x2, (void*)&B };
        launch_pdl((void*)agg2_kernel, dim3(grid), dim3(256), 0, args);
    }
    // 5) gemm2 (PDL: B staging overlaps agg2)
    {
        int grid = (B + 63) / 64;
        void* args[] = { (void*)&x2, (void*)&out, (void*)&B };
        launch_pdl((void*)gemm2_kernel, dim3(grid), dim3(256), SMEM_G2, args);
    }
}